// round 1
// baseline (speedup 1.0000x reference)
#include <cuda_runtime.h>
#include <math.h>

// Problem constants
#define BB 32
#define HH 128
#define WW 128
#define CC 64
#define MY 16
#define NKX 32   // 16 positive kx + 16 negative kx (112..127)

// ---------------------------------------------------------------------------
// Scratch (static device globals — no allocations allowed)
// ---------------------------------------------------------------------------
__device__ float g_P1r[BB * HH * MY * CC];   // 16 MB  forward-W partial, real
__device__ float g_P1i[BB * HH * MY * CC];   // 16 MB  forward-W partial, imag
__device__ float g_Xr [BB * NKX * MY * CC];  //  4 MB  forward modes, real
__device__ float g_Xi [BB * NKX * MY * CC];
__device__ float g_Yr [BB * NKX * MY * CC];  //  4 MB  mixed modes, real
__device__ float g_Yi [BB * NKX * MY * CC];
__device__ float g_Zr [BB * HH * MY * CC];   // 16 MB  inverse-H partial, real
__device__ float g_Zi [BB * HH * MY * CC];

// ---------------------------------------------------------------------------
// K1: forward DFT along W for ky = 0..15
//   P1[b,h,ky,c] = sum_w x[b,h,w,c] * exp(-2*pi*i*ky*w/128)
// One block per (b,h). 256 threads. x row (128x64) staged in smem.
// ---------------------------------------------------------------------------
__global__ __launch_bounds__(256) void k1_fwdW(const float* __restrict__ x)
{
    __shared__ float  xs[WW * CC];      // 32 KB
    __shared__ float2 tw[WW * MY];      // [w][ky], 16 KB
    const int bh = blockIdx.x;
    const int t  = threadIdx.x;

    const float4* xin = (const float4*)(x + (size_t)bh * WW * CC);
    float4* xs4 = (float4*)xs;
    for (int i = t; i < WW * CC / 4; i += 256) xs4[i] = xin[i];
    for (int i = t; i < WW * MY; i += 256) {
        int w = i >> 4, ky = i & 15;
        float s, c;
        sincospif((float)(ky * w) * (1.0f / 64.0f), &s, &c);   // theta = 2*pi*ky*w/128
        tw[i] = make_float2(c, s);                              // e^{-i theta} = c - i s
    }
    __syncthreads();

    const int ky = t & 15;
    const int g  = t >> 4;              // channel quad 0..15 -> c = 4g..4g+3
    float4 ar = make_float4(0.f, 0.f, 0.f, 0.f);
    float4 ai = make_float4(0.f, 0.f, 0.f, 0.f);
    #pragma unroll 8
    for (int w = 0; w < WW; w++) {
        float2 cs = tw[w * 16 + ky];
        float4 xv = xs4[w * 16 + g];
        ar.x += xv.x * cs.x; ar.y += xv.y * cs.x; ar.z += xv.z * cs.x; ar.w += xv.w * cs.x;
        ai.x -= xv.x * cs.y; ai.y -= xv.y * cs.y; ai.z -= xv.z * cs.y; ai.w -= xv.w * cs.y;
    }
    size_t o = ((size_t)bh * MY + ky) * CC + g * 4;
    *(float4*)(g_P1r + o) = ar;
    *(float4*)(g_P1i + o) = ai;
}

// ---------------------------------------------------------------------------
// K2: forward DFT along H at the 32 retained kx modes
//   X[b,kxi,ky,c] = sum_h P1[b,h,ky,c] * exp(-2*pi*i*kx*h/128),
//   kx = kxi (kxi<16) else 96+kxi (=112..127)
// One block per (b,ky). 256 threads.
// ---------------------------------------------------------------------------
__global__ __launch_bounds__(256) void k2_fwdH()
{
    __shared__ float2 tw[NKX * HH];         // [kxi][h], 32 KB
    __shared__ float  chr_[16 * CC];        // 4 KB h-chunk, real
    __shared__ float  chi_[16 * CC];        // 4 KB h-chunk, imag
    const int b  = blockIdx.x >> 4;
    const int ky = blockIdx.x & 15;
    const int t  = threadIdx.x;

    for (int i = t; i < NKX * HH; i += 256) {
        int kxi = i >> 7, h = i & 127;
        int kx = (kxi < 16) ? kxi : (96 + kxi);
        float s, c;
        sincospif((float)(kx * h) * (1.0f / 64.0f), &s, &c);
        tw[i] = make_float2(c, s);          // e^{-i theta}
    }

    const int kxi = t >> 3;
    const int c0  = (t & 7) * 8;
    float rr[8], ii[8];
    #pragma unroll
    for (int u = 0; u < 8; u++) { rr[u] = 0.f; ii[u] = 0.f; }

    for (int h0 = 0; h0 < HH; h0 += 16) {
        __syncthreads();
        for (int i = t; i < 16 * CC; i += 256) {
            int j = i >> 6, c = i & 63;
            size_t src = (((size_t)b * HH + h0 + j) * MY + ky) * CC + c;
            chr_[i] = g_P1r[src];
            chi_[i] = g_P1i[src];
        }
        __syncthreads();
        for (int j = 0; j < 16; j++) {
            float2 cs = tw[kxi * 128 + h0 + j];
            #pragma unroll
            for (int u = 0; u < 8; u++) {
                float xr = chr_[j * 64 + c0 + u];
                float xi = chi_[j * 64 + c0 + u];
                rr[u] += xr * cs.x + xi * cs.y;   // (xr+i*xi)(c - i*s)
                ii[u] += xi * cs.x - xr * cs.y;
            }
        }
    }
    size_t o = (((size_t)b * NKX + kxi) * MY + ky) * CC + c0;
    #pragma unroll
    for (int u = 0; u < 8; u++) { g_Xr[o + u] = rr[u]; g_Xi[o + u] = ii[u]; }
}

// ---------------------------------------------------------------------------
// K3: complex mode mixing  Y[b,:,o] = sum_i X[b,:,i] * Wc[i,o]
// One block per (kxi,ky). 256 threads. W slice + X slice staged in smem.
// ---------------------------------------------------------------------------
__global__ __launch_bounds__(256) void k3_mix(const float* __restrict__ w1r,
                                              const float* __restrict__ w1i,
                                              const float* __restrict__ w2r,
                                              const float* __restrict__ w2i)
{
    __shared__ float Xsr[BB * CC], Xsi[BB * CC];  // 16 KB
    __shared__ float Wsr[CC * CC], Wsi[CC * CC];  // 32 KB
    const int kxi = blockIdx.x >> 4;
    const int ky  = blockIdx.x & 15;
    const int t   = threadIdx.x;

    const float* wr;
    const float* wi;
    if (kxi < 16) {
        size_t off = (size_t)(kxi * 16 + ky) * CC * CC;
        wr = w1r + off; wi = w1i + off;
    } else {
        size_t off = (size_t)((kxi - 16) * 16 + ky) * CC * CC;
        wr = w2r + off; wi = w2i + off;
    }
    for (int i = t; i < CC * CC / 4; i += 256) {
        ((float4*)Wsr)[i] = ((const float4*)wr)[i];
        ((float4*)Wsi)[i] = ((const float4*)wi)[i];
    }
    for (int i = t; i < BB * CC; i += 256) {
        int b = i >> 6, c = i & 63;
        size_t src = (((size_t)b * NKX + kxi) * MY + ky) * CC + c;
        Xsr[i] = g_Xr[src];
        Xsi[i] = g_Xi[src];
    }
    __syncthreads();

    const int o  = t & 63;
    const int bg = t >> 6;
    float yr[8], yi[8];
    #pragma unroll
    for (int j = 0; j < 8; j++) { yr[j] = 0.f; yi[j] = 0.f; }

    for (int i = 0; i < CC; i++) {
        float wrv = Wsr[i * 64 + o];
        float wiv = Wsi[i * 64 + o];
        #pragma unroll
        for (int j = 0; j < 8; j++) {
            int b = bg * 8 + j;
            float xr = Xsr[b * 64 + i];
            float xi = Xsi[b * 64 + i];
            yr[j] += xr * wrv - xi * wiv;
            yi[j] += xr * wiv + xi * wrv;
        }
    }
    #pragma unroll
    for (int j = 0; j < 8; j++) {
        size_t dst = (((size_t)(bg * 8 + j) * NKX + kxi) * MY + ky) * CC + o;
        g_Yr[dst] = yr[j];
        g_Yi[dst] = yi[j];
    }
}

// ---------------------------------------------------------------------------
// K4: inverse DFT along H (with 1/H folded in)
//   Z[b,h,ky,c] = (1/128) sum_kxi Y[b,kxi,ky,c] * exp(+2*pi*i*kx*h/128)
// One block per (b,ky). 256 threads; Y slice held in registers per thread.
// ---------------------------------------------------------------------------
__global__ __launch_bounds__(256) void k4_invH()
{
    __shared__ float  Ysr[NKX * CC], Ysi[NKX * CC];  // 16 KB
    __shared__ float2 tw[HH * NKX];                  // [h][kxi], 32 KB
    const int b  = blockIdx.x >> 4;
    const int ky = blockIdx.x & 15;
    const int t  = threadIdx.x;

    for (int i = t; i < HH * NKX; i += 256) {
        int h = i >> 5, kxi = i & 31;
        int kx = (kxi < 16) ? kxi : (96 + kxi);
        float s, c;
        sincospif((float)(kx * h) * (1.0f / 64.0f), &s, &c);
        tw[i] = make_float2(c * (1.0f / 128.0f), s * (1.0f / 128.0f));  // e^{+i theta}/H
    }
    for (int i = t; i < NKX * CC; i += 256) {
        int kxi = i >> 6, c = i & 63;
        size_t src = (((size_t)b * NKX + kxi) * MY + ky) * CC + c;
        Ysr[i] = g_Yr[src];
        Ysi[i] = g_Yi[src];
    }
    __syncthreads();

    const int c  = t & 63;
    const int hg = t >> 6;
    float yrr[NKX], yii[NKX];
    #pragma unroll
    for (int k = 0; k < NKX; k++) {
        yrr[k] = Ysr[k * 64 + c];
        yii[k] = Ysi[k * 64 + c];
    }
    for (int j = 0; j < 32; j++) {
        int h = hg * 32 + j;
        float zr = 0.f, zi = 0.f;
        const float4* twr = (const float4*)(tw + h * NKX);
        #pragma unroll
        for (int q = 0; q < 16; q++) {
            float4 tq = twr[q];
            zr += yrr[2 * q] * tq.x - yii[2 * q] * tq.y;
            zi += yrr[2 * q] * tq.y + yii[2 * q] * tq.x;
            zr += yrr[2 * q + 1] * tq.z - yii[2 * q + 1] * tq.w;
            zi += yrr[2 * q + 1] * tq.w + yii[2 * q + 1] * tq.z;
        }
        size_t o = (((size_t)b * HH + h) * MY + ky) * CC + c;
        g_Zr[o] = zr;
        g_Zi[o] = zi;
    }
}

// ---------------------------------------------------------------------------
// K5: fused inverse-rfft along W + dense branch + residual + tanh-GELU
//   y_s[w,c] = sum_{ky=0..15} (Re Z)*twc - (Im Z)*tws,  tw scaled 1/W (2/W for ky>0)
//   y_p[w,c] = sum_i x[w,i] K[i,c] + bias[c]
//   out = gelu_tanh(x + y_s + y_p)
// One block per (b,h). 256 threads; K column + Z modes live in registers.
// ---------------------------------------------------------------------------
__global__ __launch_bounds__(256) void k5_final(const float* __restrict__ x,
                                                const float* __restrict__ dk,
                                                const float* __restrict__ bias,
                                                float* __restrict__ out)
{
    __shared__ float  xs[WW * CC];      // 32 KB
    __shared__ float2 tw[WW * MY];      // [w][ky], 16 KB
    const int bh = blockIdx.x;
    const int t  = threadIdx.x;

    const float4* xin = (const float4*)(x + (size_t)bh * WW * CC);
    float4* xs4 = (float4*)xs;
    for (int i = t; i < WW * CC / 4; i += 256) xs4[i] = xin[i];
    for (int i = t; i < WW * MY; i += 256) {
        int w = i >> 4, ky = i & 15;
        float s, c;
        sincospif((float)(ky * w) * (1.0f / 64.0f), &s, &c);    // e^{+i theta}
        float sc = (ky == 0) ? (1.0f / 128.0f) : (2.0f / 128.0f);
        tw[i] = make_float2(c * sc, s * sc);
    }
    __syncthreads();

    const int c  = t & 63;
    const int wg = t >> 6;

    float kc[CC];
    #pragma unroll
    for (int i = 0; i < CC; i++) kc[i] = __ldg(dk + i * 64 + c);

    float zr[MY], zi[MY];
    {
        size_t zb = (size_t)bh * MY * CC + c;
        #pragma unroll
        for (int k = 0; k < MY; k++) {
            zr[k] = g_Zr[zb + (size_t)k * CC];
            zi[k] = g_Zi[zb + (size_t)k * CC];
        }
    }
    const float bc = __ldg(bias + c);

    for (int j = 0; j < 32; j++) {
        int w = wg * 32 + j;
        float acc = bc;
        const float4* xr4 = xs4 + w * 16;
        #pragma unroll
        for (int q = 0; q < 16; q++) {
            float4 xq = xr4[q];
            acc += xq.x * kc[4 * q] + xq.y * kc[4 * q + 1]
                 + xq.z * kc[4 * q + 2] + xq.w * kc[4 * q + 3];
        }
        float res = xs[w * 64 + c];
        float ys = 0.f;
        const float4* twr = (const float4*)(tw + w * 16);
        #pragma unroll
        for (int q = 0; q < 8; q++) {
            float4 tq = twr[q];
            ys += zr[2 * q] * tq.x - zi[2 * q] * tq.y;
            ys += zr[2 * q + 1] * tq.z - zi[2 * q + 1] * tq.w;
        }
        float s = res + ys + acc;
        // tanh-GELU: 0.5*s*(1+tanh(sqrt(2/pi)*(s+0.044715 s^3))) = s*sigmoid(2u)
        float u = 0.7978845608028654f * (s + 0.044715f * s * s * s);
        float g = s * __frcp_rn(1.0f + __expf(-2.0f * u));
        out[(size_t)bh * WW * CC + (size_t)w * CC + c] = g;
    }
}

// ---------------------------------------------------------------------------
// Launch
// ---------------------------------------------------------------------------
extern "C" void kernel_launch(void* const* d_in, const int* in_sizes, int n_in,
                              void* d_out, int out_size)
{
    const float* x   = (const float*)d_in[0];
    const float* w1r = (const float*)d_in[1];
    const float* w1i = (const float*)d_in[2];
    const float* w2r = (const float*)d_in[3];
    const float* w2i = (const float*)d_in[4];
    const float* dk  = (const float*)d_in[5];
    const float* db  = (const float*)d_in[6];
    float* out = (float*)d_out;

    k1_fwdW <<<BB * HH, 256>>>(x);
    k2_fwdH <<<BB * MY, 256>>>();
    k3_mix  <<<NKX * MY, 256>>>(w1r, w1i, w2r, w2i);
    k4_invH <<<BB * MY, 256>>>();
    k5_final<<<BB * HH, 256>>>(x, dk, db, out);
}

// round 3
// speedup vs baseline: 1.3521x; 1.3521x over previous
#include <cuda_runtime.h>
#include <cuda_bf16.h>
#include <math.h>
#include <cstdint>

// Problem constants
#define BB 32
#define HH 128
#define WW 128
#define CC 64
#define MY 16
#define NKX 32   // 16 positive kx + 16 negative kx (112..127)

// ---------------------------------------------------------------------------
// Scratch (static device globals — no allocations allowed)
// ---------------------------------------------------------------------------
__device__ float g_P1r[BB * HH * MY * CC];
__device__ float g_P1i[BB * HH * MY * CC];
__device__ float g_Xr [BB * NKX * MY * CC];
__device__ float g_Xi [BB * NKX * MY * CC];
__device__ float g_Yr [BB * NKX * MY * CC];
__device__ float g_Yi [BB * NKX * MY * CC];
__device__ float g_Zr [BB * HH * MY * CC];
__device__ float g_Zi [BB * HH * MY * CC];

// Precomputed bf16 operands for the K5 GEMM
__device__ __align__(16) __nv_bfloat16 g_T [WW * 32];     // [w][j]: j<16 cos*sc, j>=16 -sin*sc
__device__ __align__(16) __nv_bfloat16 g_Bk[CC * 128];    // [c][k]: K_hi(64) | K_lo(64)

// ---------------------------------------------------------------------------
// mma.sync helpers (baseline PTX, legal on target sm_103)
// ---------------------------------------------------------------------------
__device__ __forceinline__ uint32_t smem_u32(const void* p) {
    uint32_t a;
    asm("{ .reg .u64 t; cvta.to.shared.u64 t, %1; cvt.u32.u64 %0, t; }" : "=r"(a) : "l"(p));
    return a;
}
#define LDSM4(r0, r1, r2, r3, addr) \
    asm volatile("ldmatrix.sync.aligned.m8n8.x4.shared.b16 {%0,%1,%2,%3}, [%4];" \
        : "=r"(r0), "=r"(r1), "=r"(r2), "=r"(r3) : "r"(addr))

#define MMA16816(d, a0, a1, a2, a3, b0, b1) \
    asm volatile("mma.sync.aligned.m16n8k16.row.col.f32.bf16.bf16.f32 " \
        "{%0,%1,%2,%3}, {%4,%5,%6,%7}, {%8,%9}, {%0,%1,%2,%3};" \
        : "+f"((d)[0]), "+f"((d)[1]), "+f"((d)[2]), "+f"((d)[3]) \
        : "r"(a0), "r"(a1), "r"(a2), "r"(a3), "r"(b0), "r"(b1))

__device__ __forceinline__ uint32_t pack2(__nv_bfloat16 a, __nv_bfloat16 b) {
    return (uint32_t)__bfloat16_as_ushort(a) | ((uint32_t)__bfloat16_as_ushort(b) << 16);
}
__device__ __forceinline__ float bflo(uint32_t u) {
    return __bfloat162float(__ushort_as_bfloat16((unsigned short)(u & 0xFFFF)));
}
__device__ __forceinline__ float bfhi(uint32_t u) {
    return __bfloat162float(__ushort_as_bfloat16((unsigned short)(u >> 16)));
}

// ---------------------------------------------------------------------------
// K0: per-launch precompute of bf16 GEMM operands
// ---------------------------------------------------------------------------
__global__ void k0_init(const float* __restrict__ dk)
{
    int t = threadIdx.x + blockIdx.x * blockDim.x;
    int stride = blockDim.x * gridDim.x;
    for (int i = t; i < WW * 32; i += stride) {
        int w = i >> 5, j = i & 31, ky = j & 15;
        float s, c;
        sincospif((float)(ky * w) * (1.0f / 64.0f), &s, &c);
        float sc = (ky == 0) ? (1.0f / 128.0f) : (2.0f / 128.0f);
        g_T[i] = __float2bfloat16_rn((j < 16) ? c * sc : -s * sc);
    }
    for (int i = t; i < CC * 128; i += stride) {
        int c = i >> 7, k = i & 127;
        int kk = k & 63;
        float v = dk[kk * 64 + c];
        __nv_bfloat16 hi = __float2bfloat16_rn(v);
        g_Bk[i] = (k < 64) ? hi : __float2bfloat16_rn(v - __bfloat162float(hi));
    }
}

// ---------------------------------------------------------------------------
// K1: forward DFT along W for ky = 0..15  (fp32)
// ---------------------------------------------------------------------------
__global__ __launch_bounds__(256) void k1_fwdW(const float* __restrict__ x)
{
    __shared__ float  xs[WW * CC];
    __shared__ float2 tw[WW * MY];
    const int bh = blockIdx.x;
    const int t  = threadIdx.x;

    const float4* xin = (const float4*)(x + (size_t)bh * WW * CC);
    float4* xs4 = (float4*)xs;
    for (int i = t; i < WW * CC / 4; i += 256) xs4[i] = xin[i];
    for (int i = t; i < WW * MY; i += 256) {
        int w = i >> 4, ky = i & 15;
        float s, c;
        sincospif((float)(ky * w) * (1.0f / 64.0f), &s, &c);
        tw[i] = make_float2(c, s);
    }
    __syncthreads();

    const int ky = t & 15;
    const int g  = t >> 4;
    float4 ar = make_float4(0.f, 0.f, 0.f, 0.f);
    float4 ai = make_float4(0.f, 0.f, 0.f, 0.f);
    #pragma unroll 8
    for (int w = 0; w < WW; w++) {
        float2 cs = tw[w * 16 + ky];
        float4 xv = xs4[w * 16 + g];
        ar.x += xv.x * cs.x; ar.y += xv.y * cs.x; ar.z += xv.z * cs.x; ar.w += xv.w * cs.x;
        ai.x -= xv.x * cs.y; ai.y -= xv.y * cs.y; ai.z -= xv.z * cs.y; ai.w -= xv.w * cs.y;
    }
    size_t o = ((size_t)bh * MY + ky) * CC + g * 4;
    *(float4*)(g_P1r + o) = ar;
    *(float4*)(g_P1i + o) = ai;
}

// ---------------------------------------------------------------------------
// K2: forward DFT along H at the 32 retained kx modes (fp32)
// ---------------------------------------------------------------------------
__global__ __launch_bounds__(256) void k2_fwdH()
{
    __shared__ float2 tw[NKX * HH];
    __shared__ float  chr_[16 * CC];
    __shared__ float  chi_[16 * CC];
    const int b  = blockIdx.x >> 4;
    const int ky = blockIdx.x & 15;
    const int t  = threadIdx.x;

    for (int i = t; i < NKX * HH; i += 256) {
        int kxi = i >> 7, h = i & 127;
        int kx = (kxi < 16) ? kxi : (96 + kxi);
        float s, c;
        sincospif((float)(kx * h) * (1.0f / 64.0f), &s, &c);
        tw[i] = make_float2(c, s);
    }

    const int kxi = t >> 3;
    const int c0  = (t & 7) * 8;
    float rr[8], ii[8];
    #pragma unroll
    for (int u = 0; u < 8; u++) { rr[u] = 0.f; ii[u] = 0.f; }

    for (int h0 = 0; h0 < HH; h0 += 16) {
        __syncthreads();
        for (int i = t; i < 16 * CC; i += 256) {
            int j = i >> 6, c = i & 63;
            size_t src = (((size_t)b * HH + h0 + j) * MY + ky) * CC + c;
            chr_[i] = g_P1r[src];
            chi_[i] = g_P1i[src];
        }
        __syncthreads();
        for (int j = 0; j < 16; j++) {
            float2 cs = tw[kxi * 128 + h0 + j];
            #pragma unroll
            for (int u = 0; u < 8; u++) {
                float xr = chr_[j * 64 + c0 + u];
                float xi = chi_[j * 64 + c0 + u];
                rr[u] += xr * cs.x + xi * cs.y;
                ii[u] += xi * cs.x - xr * cs.y;
            }
        }
    }
    size_t o = (((size_t)b * NKX + kxi) * MY + ky) * CC + c0;
    #pragma unroll
    for (int u = 0; u < 8; u++) { g_Xr[o + u] = rr[u]; g_Xi[o + u] = ii[u]; }
}

// ---------------------------------------------------------------------------
// K3: complex mode mixing (fp32)
// ---------------------------------------------------------------------------
__global__ __launch_bounds__(256) void k3_mix(const float* __restrict__ w1r,
                                              const float* __restrict__ w1i,
                                              const float* __restrict__ w2r,
                                              const float* __restrict__ w2i)
{
    __shared__ float Xsr[BB * CC], Xsi[BB * CC];
    __shared__ float Wsr[CC * CC], Wsi[CC * CC];
    const int kxi = blockIdx.x >> 4;
    const int ky  = blockIdx.x & 15;
    const int t   = threadIdx.x;

    const float* wr;
    const float* wi;
    if (kxi < 16) {
        size_t off = (size_t)(kxi * 16 + ky) * CC * CC;
        wr = w1r + off; wi = w1i + off;
    } else {
        size_t off = (size_t)((kxi - 16) * 16 + ky) * CC * CC;
        wr = w2r + off; wi = w2i + off;
    }
    for (int i = t; i < CC * CC / 4; i += 256) {
        ((float4*)Wsr)[i] = ((const float4*)wr)[i];
        ((float4*)Wsi)[i] = ((const float4*)wi)[i];
    }
    for (int i = t; i < BB * CC; i += 256) {
        int b = i >> 6, c = i & 63;
        size_t src = (((size_t)b * NKX + kxi) * MY + ky) * CC + c;
        Xsr[i] = g_Xr[src];
        Xsi[i] = g_Xi[src];
    }
    __syncthreads();

    const int o  = t & 63;
    const int bg = t >> 6;
    float yr[8], yi[8];
    #pragma unroll
    for (int j = 0; j < 8; j++) { yr[j] = 0.f; yi[j] = 0.f; }

    for (int i = 0; i < CC; i++) {
        float wrv = Wsr[i * 64 + o];
        float wiv = Wsi[i * 64 + o];
        #pragma unroll
        for (int j = 0; j < 8; j++) {
            int b = bg * 8 + j;
            float xr = Xsr[b * 64 + i];
            float xi = Xsi[b * 64 + i];
            yr[j] += xr * wrv - xi * wiv;
            yi[j] += xr * wiv + xi * wrv;
        }
    }
    #pragma unroll
    for (int j = 0; j < 8; j++) {
        size_t dst = (((size_t)(bg * 8 + j) * NKX + kxi) * MY + ky) * CC + o;
        g_Yr[dst] = yr[j];
        g_Yi[dst] = yi[j];
    }
}

// ---------------------------------------------------------------------------
// K4: inverse DFT along H (fp32)
// ---------------------------------------------------------------------------
__global__ __launch_bounds__(256) void k4_invH()
{
    __shared__ float  Ysr[NKX * CC], Ysi[NKX * CC];
    __shared__ float2 tw[HH * NKX];
    const int b  = blockIdx.x >> 4;
    const int ky = blockIdx.x & 15;
    const int t  = threadIdx.x;

    for (int i = t; i < HH * NKX; i += 256) {
        int h = i >> 5, kxi = i & 31;
        int kx = (kxi < 16) ? kxi : (96 + kxi);
        float s, c;
        sincospif((float)(kx * h) * (1.0f / 64.0f), &s, &c);
        tw[i] = make_float2(c * (1.0f / 128.0f), s * (1.0f / 128.0f));
    }
    for (int i = t; i < NKX * CC; i += 256) {
        int kxi = i >> 6, c = i & 63;
        size_t src = (((size_t)b * NKX + kxi) * MY + ky) * CC + c;
        Ysr[i] = g_Yr[src];
        Ysi[i] = g_Yi[src];
    }
    __syncthreads();

    const int c  = t & 63;
    const int hg = t >> 6;
    float yrr[NKX], yii[NKX];
    #pragma unroll
    for (int k = 0; k < NKX; k++) {
        yrr[k] = Ysr[k * 64 + c];
        yii[k] = Ysi[k * 64 + c];
    }
    for (int j = 0; j < 32; j++) {
        int h = hg * 32 + j;
        float zr = 0.f, zi = 0.f;
        const float4* twr = (const float4*)(tw + h * NKX);
        #pragma unroll
        for (int q = 0; q < 16; q++) {
            float4 tq = twr[q];
            zr += yrr[2 * q] * tq.x - yii[2 * q] * tq.y;
            zi += yrr[2 * q] * tq.y + yii[2 * q] * tq.x;
            zr += yrr[2 * q + 1] * tq.z - yii[2 * q + 1] * tq.w;
            zi += yrr[2 * q + 1] * tq.w + yii[2 * q + 1] * tq.z;
        }
        size_t o = (((size_t)b * HH + h) * MY + ky) * CC + c;
        g_Zr[o] = zr;
        g_Zi[o] = zi;
    }
}

// ---------------------------------------------------------------------------
// K5: mma.sync bf16 GEMM per (b,h)
//   A[128 x 160] = [ x_hi(64) | x_lo(64) | T(32) ]           (row-major, stride 168)
//   B[ 64 x 160] = [ K_hi(64) | K_lo(64) | Zr,Zi(32) ]       (row-major, stride 168)
//   D[w][c] = x_hi.K_hi + x_hi.K_lo + x_lo.K_hi + T.Z        (4 pass pairs, 14 ksteps)
//   out = gelu_tanh(D + (x_hi + x_lo) + bias)
// ---------------------------------------------------------------------------
#define SA 168
#define K5_BIAS 0
#define K5_A    256
#define K5_B    (256 + 128 * SA * 2)
#define K5_SMEM (K5_B + 64 * SA * 2)

__global__ __launch_bounds__(256) void k5_mma(const float* __restrict__ x,
                                              const float* __restrict__ bias,
                                              float* __restrict__ out)
{
    extern __shared__ char smem[];
    const uint32_t sbase = smem_u32(smem);
    const int bh   = blockIdx.x;
    const int t    = threadIdx.x;
    const int warp = t >> 5;
    const int lane = t & 31;

    // ---- Fill A: x_hi (cols 0..63) and x_lo (64..127); 2 threads per row ----
    {
        const int w  = t >> 1;
        const int c0 = (t & 1) * 32;
        const float4* xr4 = (const float4*)(x + (size_t)bh * 8192 + (size_t)w * 64 + c0);
        #pragma unroll
        for (int ch = 0; ch < 4; ch++) {
            uint32_t uh[2], ul[2];
            #pragma unroll
            for (int q = 0; q < 2; q++) {
                float4 v = xr4[ch * 2 + q];
                __nv_bfloat16 h0 = __float2bfloat16_rn(v.x), h1 = __float2bfloat16_rn(v.y);
                __nv_bfloat16 h2 = __float2bfloat16_rn(v.z), h3 = __float2bfloat16_rn(v.w);
                uh[q] = pack2(h0, h1);
                ul[q] = pack2(__float2bfloat16_rn(v.x - __bfloat162float(h0)),
                              __float2bfloat16_rn(v.y - __bfloat162float(h1)));
                uint32_t uh2 = pack2(h2, h3);
                uint32_t ul2 = pack2(__float2bfloat16_rn(v.z - __bfloat162float(h2)),
                                     __float2bfloat16_rn(v.w - __bfloat162float(h3)));
                // store pairs interleaved into local regs
                if (q == 0) { *(uint2*)(smem + K5_A + (w * SA + c0 + ch * 8) * 2)      = make_uint2(uh[0], uh2);
                              *(uint2*)(smem + K5_A + (w * SA + 64 + c0 + ch * 8) * 2) = make_uint2(ul[0], ul2); }
                else        { *(uint2*)(smem + K5_A + (w * SA + c0 + ch * 8 + 4) * 2)      = make_uint2(uh[1], uh2);
                              *(uint2*)(smem + K5_A + (w * SA + 64 + c0 + ch * 8 + 4) * 2) = make_uint2(ul[1], ul2); }
            }
        }
    }
    // ---- Fill A: T block (cols 128..159) ----
    if (t < 128) {
        const int w = t;
        const uint4* ts = (const uint4*)(g_T + w * 32);
        #pragma unroll
        for (int ch = 0; ch < 4; ch++)
            *(uint4*)(smem + K5_A + (w * SA + 128 + ch * 8) * 2) = ts[ch];
    }
    // ---- Fill B ----
    {
        const int c = t >> 2;
        const int q = t & 3;
        if (q < 2) {
            const uint4* src = (const uint4*)(g_Bk + c * 128 + q * 64);
            #pragma unroll
            for (int ch = 0; ch < 8; ch++)
                *(uint4*)(smem + K5_B + (c * SA + q * 64 + ch * 8) * 2) = src[ch];
        } else {
            const float* zsrc = (q == 2) ? g_Zr : g_Zi;
            const size_t zb = (size_t)bh * MY * CC + c;
            uint32_t u[8];
            #pragma unroll
            for (int k = 0; k < 8; k++)
                u[k] = pack2(__float2bfloat16_rn(zsrc[zb + (size_t)(2 * k) * CC]),
                             __float2bfloat16_rn(zsrc[zb + (size_t)(2 * k + 1) * CC]));
            int col = 128 + (q - 2) * 16;
            *(uint4*)(smem + K5_B + (c * SA + col) * 2)     = make_uint4(u[0], u[1], u[2], u[3]);
            *(uint4*)(smem + K5_B + (c * SA + col + 8) * 2) = make_uint4(u[4], u[5], u[6], u[7]);
        }
    }
    if (t < 64) ((float*)(smem + K5_BIAS))[t] = bias[t];

    __syncthreads();

    // ---- Compute: warp handles rows 16*warp .. +15 ----
    float acc[8][4];
    #pragma unroll
    for (int nt = 0; nt < 8; nt++) {
        acc[nt][0] = 0.f; acc[nt][1] = 0.f; acc[nt][2] = 0.f; acc[nt][3] = 0.f;
    }

    const int arow  = warp * 16 + (lane & 7) + ((lane >> 3) & 1) * 8;
    const int akoff = (lane >> 4) * 8;
    const int brow  = (lane & 7) + (lane >> 4) * 8;   // extra +8 rows for m2,m3 (next n-tile)
    const int bkoff = ((lane >> 3) & 1) * 8;

    const int passes[4][3] = { {0, 0, 4}, {0, 64, 4}, {64, 0, 4}, {128, 128, 2} };
    #pragma unroll
    for (int p = 0; p < 4; p++) {
        const int kA = passes[p][0], kB = passes[p][1], nks = passes[p][2];
        #pragma unroll
        for (int ks = 0; ks < 4; ks++) {
            if (ks >= nks) break;
            uint32_t a0, a1, a2, a3;
            uint32_t aaddr = sbase + K5_A + (uint32_t)(arow * SA + kA + ks * 16 + akoff) * 2;
            LDSM4(a0, a1, a2, a3, aaddr);
            #pragma unroll
            for (int nt2 = 0; nt2 < 4; nt2++) {
                uint32_t b0, b1, b2, b3;
                uint32_t baddr = sbase + K5_B
                    + (uint32_t)((nt2 * 16 + brow) * SA + kB + ks * 16 + bkoff) * 2;
                LDSM4(b0, b1, b2, b3, baddr);
                MMA16816(acc[2 * nt2],     a0, a1, a2, a3, b0, b1);
                MMA16816(acc[2 * nt2 + 1], a0, a1, a2, a3, b2, b3);
            }
        }
    }

    // ---- Epilogue ----
    const int r0 = warp * 16 + (lane >> 2);
    const float* bs = (const float*)(smem + K5_BIAS);
    #pragma unroll
    for (int half = 0; half < 2; half++) {
        const int r = r0 + half * 8;
        float* orow = out + (size_t)bh * 8192 + (size_t)r * 64;
        #pragma unroll
        for (int nt = 0; nt < 8; nt++) {
            const int c = nt * 8 + 2 * (lane & 3);
            uint32_t hp = *(const uint32_t*)(smem + K5_A + (r * SA + c) * 2);
            uint32_t lp = *(const uint32_t*)(smem + K5_A + (r * SA + 64 + c) * 2);
            float res0 = bflo(hp) + bflo(lp);
            float res1 = bfhi(hp) + bfhi(lp);
            float s0 = acc[nt][half * 2 + 0] + res0 + bs[c];
            float s1 = acc[nt][half * 2 + 1] + res1 + bs[c + 1];
            float u0 = 0.7978845608028654f * (s0 + 0.044715f * s0 * s0 * s0);
            float u1 = 0.7978845608028654f * (s1 + 0.044715f * s1 * s1 * s1);
            float g0 = s0 * __frcp_rn(1.0f + __expf(-2.0f * u0));
            float g1 = s1 * __frcp_rn(1.0f + __expf(-2.0f * u1));
            *(float2*)(orow + c) = make_float2(g0, g1);
        }
    }
}

// ---------------------------------------------------------------------------
// Launch
// ---------------------------------------------------------------------------
extern "C" void kernel_launch(void* const* d_in, const int* in_sizes, int n_in,
                              void* d_out, int out_size)
{
    const float* x   = (const float*)d_in[0];
    const float* w1r = (const float*)d_in[1];
    const float* w1i = (const float*)d_in[2];
    const float* w2r = (const float*)d_in[3];
    const float* w2i = (const float*)d_in[4];
    const float* dk  = (const float*)d_in[5];
    const float* db  = (const float*)d_in[6];
    float* out = (float*)d_out;

    static int configured = 0;
    if (!configured) {
        cudaFuncSetAttribute(k5_mma, cudaFuncAttributeMaxDynamicSharedMemorySize, K5_SMEM);
        configured = 1;
    }

    k0_init <<<48, 256>>>(dk);
    k1_fwdW <<<BB * HH, 256>>>(x);
    k2_fwdH <<<BB * MY, 256>>>();
    k3_mix  <<<NKX * MY, 256>>>(w1r, w1i, w2r, w2i);
    k4_invH <<<BB * MY, 256>>>();
    k5_mma  <<<BB * HH, 256, K5_SMEM>>>(x, db, out);
}

// round 5
// speedup vs baseline: 1.8602x; 1.3758x over previous
#include <cuda_runtime.h>
#include <cuda_bf16.h>
#include <math.h>
#include <cstdint>

// Problem constants
#define BB 32
#define HH 128
#define WW 128
#define CC 64
#define MY 16
#define NKX 32   // 16 positive kx + 16 negative kx (112..127)

// ---------------------------------------------------------------------------
// Scratch (static device globals — no allocations allowed)
// ---------------------------------------------------------------------------
__device__ float g_Xr [BB * NKX * MY * CC];
__device__ float g_Xi [BB * NKX * MY * CC];
__device__ float g_Yr [BB * NKX * MY * CC];
__device__ float g_Yi [BB * NKX * MY * CC];
__device__ float g_Zr [BB * HH * MY * CC];
__device__ float g_Zi [BB * HH * MY * CC];

// bf16 scratch / precomputed GEMM operands
__device__ __align__(16) __nv_bfloat16 g_P1b[BB * MY * 256 * CC]; // [b][ky][h*2+p][c]
__device__ __align__(16) __nv_bfloat16 g_F2 [32 * 128];           // [ky*2+p][w]
__device__ __align__(16) __nv_bfloat16 g_G2 [64 * 256];           // [kxi*2+p][h*2+q]
__device__ __align__(16) __nv_bfloat16 g_T  [WW * 32];            // [w][j] inverse-W DFT
__device__ __align__(16) __nv_bfloat16 g_Bk [CC * 128];           // [c][k]: K_hi(64)|K_lo(64)

// ---------------------------------------------------------------------------
// mma.sync helpers (baseline PTX, legal on target sm_103)
// ---------------------------------------------------------------------------
__device__ __forceinline__ uint32_t smem_u32(const void* p) {
    uint32_t a;
    asm("{ .reg .u64 t; cvta.to.shared.u64 t, %1; cvt.u32.u64 %0, t; }" : "=r"(a) : "l"(p));
    return a;
}
#define LDSM4(r0, r1, r2, r3, addr) \
    asm volatile("ldmatrix.sync.aligned.m8n8.x4.shared.b16 {%0,%1,%2,%3}, [%4];" \
        : "=r"(r0), "=r"(r1), "=r"(r2), "=r"(r3) : "r"(addr))
#define LDSM4T(r0, r1, r2, r3, addr) \
    asm volatile("ldmatrix.sync.aligned.m8n8.x4.trans.shared.b16 {%0,%1,%2,%3}, [%4];" \
        : "=r"(r0), "=r"(r1), "=r"(r2), "=r"(r3) : "r"(addr))

#define MMA16816(d, a0, a1, a2, a3, b0, b1) \
    asm volatile("mma.sync.aligned.m16n8k16.row.col.f32.bf16.bf16.f32 " \
        "{%0,%1,%2,%3}, {%4,%5,%6,%7}, {%8,%9}, {%0,%1,%2,%3};" \
        : "+f"((d)[0]), "+f"((d)[1]), "+f"((d)[2]), "+f"((d)[3]) \
        : "r"(a0), "r"(a1), "r"(a2), "r"(a3), "r"(b0), "r"(b1))

__device__ __forceinline__ uint32_t pack2(__nv_bfloat16 a, __nv_bfloat16 b) {
    return (uint32_t)__bfloat16_as_ushort(a) | ((uint32_t)__bfloat16_as_ushort(b) << 16);
}
__device__ __forceinline__ float bflo(uint32_t u) {
    return __bfloat162float(__ushort_as_bfloat16((unsigned short)(u & 0xFFFF)));
}
__device__ __forceinline__ float bfhi(uint32_t u) {
    return __bfloat162float(__ushort_as_bfloat16((unsigned short)(u >> 16)));
}

// ---------------------------------------------------------------------------
// K0: per-launch precompute of bf16 operands
// ---------------------------------------------------------------------------
__global__ void k0_init(const float* __restrict__ dk)
{
    int t = threadIdx.x + blockIdx.x * blockDim.x;
    int stride = blockDim.x * gridDim.x;
    // F2[m=ky*2+p][w]: p=0 cos, p=1 -sin of 2*pi*ky*w/128
    for (int i = t; i < 32 * 128; i += stride) {
        int m = i >> 7, w = i & 127;
        int ky = m >> 1, p = m & 1;
        float s, c;
        sincospif((float)(ky * w) * (1.0f / 64.0f), &s, &c);
        g_F2[i] = __float2bfloat16_rn(p == 0 ? c : -s);
    }
    // G2[m=kxi*2+p][k=h*2+q]: complex twiddle e^{-i th} as real 2x2 blocks
    for (int i = t; i < 64 * 256; i += stride) {
        int m = i >> 8, k = i & 255;
        int kxi = m >> 1, p = m & 1;
        int h = k >> 1, q = k & 1;
        int kx = (kxi < 16) ? kxi : (96 + kxi);
        float s, c;
        sincospif((float)(kx * h) * (1.0f / 64.0f), &s, &c);
        float v = (p == 0) ? (q == 0 ? c : s) : (q == 0 ? -s : c);
        g_G2[i] = __float2bfloat16_rn(v);
    }
    // T[w][j]: j<16 cos*sc, j>=16 -sin*sc (inverse-W with rfft folding)
    for (int i = t; i < WW * 32; i += stride) {
        int w = i >> 5, j = i & 31, ky = j & 15;
        float s, c;
        sincospif((float)(ky * w) * (1.0f / 64.0f), &s, &c);
        float sc = (ky == 0) ? (1.0f / 128.0f) : (2.0f / 128.0f);
        g_T[i] = __float2bfloat16_rn((j < 16) ? c * sc : -s * sc);
    }
    // Bk[c][k]: K_hi | K_lo (dense kernel transposed, hi/lo split)
    for (int i = t; i < CC * 128; i += stride) {
        int c = i >> 7, k = i & 127;
        int kk = k & 63;
        float v = dk[kk * 64 + c];
        __nv_bfloat16 hi = __float2bfloat16_rn(v);
        g_Bk[i] = (k < 64) ? hi : __float2bfloat16_rn(v - __bfloat162float(hi));
    }
}

// ---------------------------------------------------------------------------
// K1 (mma): per (b,h): P1[32 m=(ky,p), 64 c] = F2[32x128] @ x[128 w, 64 c]
// 4 h-slices per CTA (8 warps: warp = 2*hl + nhalf)
// ---------------------------------------------------------------------------
#define K1_SA 136
#define K1_SX 72
#define K1_SMEM_A 0
#define K1_SMEM_X (32 * K1_SA * 2)                      // 8704
#define K1_SMEM_TOTAL (K1_SMEM_X + 4 * 128 * K1_SX * 2) // 82432

__global__ __launch_bounds__(256) void k1_mma(const float* __restrict__ x)
{
    extern __shared__ char sm[];
    const uint32_t sbase = smem_u32(sm);
    const int b    = blockIdx.x >> 5;
    const int hg   = blockIdx.x & 31;
    const int t    = threadIdx.x;
    const int warp = t >> 5;
    const int lane = t & 31;

    // stage F2 (padded stride 136)
    {
        const uint32_t* src = (const uint32_t*)g_F2;
        for (int i = t; i < 32 * 64; i += 256) {
            int m = i >> 6, kp = i & 63;
            *(uint32_t*)(sm + K1_SMEM_A + m * K1_SA * 2 + kp * 4) = src[i];
        }
    }
    // stage x (4 h), fp32 -> bf16, layout [hl][w][72]
    {
        const float4* xin = (const float4*)(x + ((size_t)(b * HH + hg * 4)) * WW * CC);
        for (int i = t; i < 4 * 128 * 16; i += 256) {
            float4 v = xin[i];
            int hl = i >> 11, w = (i >> 4) & 127, c4 = i & 15;
            uint32_t u0 = pack2(__float2bfloat16_rn(v.x), __float2bfloat16_rn(v.y));
            uint32_t u1 = pack2(__float2bfloat16_rn(v.z), __float2bfloat16_rn(v.w));
            *(uint2*)(sm + K1_SMEM_X + ((hl * 128 + w) * K1_SX + c4 * 4) * 2) = make_uint2(u0, u1);
        }
    }
    __syncthreads();

    const int hl = warp >> 1, nh = warp & 1;
    const uint32_t Ab = sbase + K1_SMEM_A;
    const uint32_t Xb = sbase + K1_SMEM_X + hl * 128 * K1_SX * 2;

    float acc[2][4][4];
    #pragma unroll
    for (int mt = 0; mt < 2; mt++)
        #pragma unroll
        for (int nt = 0; nt < 4; nt++)
            #pragma unroll
            for (int q = 0; q < 4; q++) acc[mt][nt][q] = 0.f;

    const int arow = lane & 15;
    const int acol = (lane >> 4) * 8;
    const int brow = (lane & 7) + ((lane >> 3) & 1) * 8;
    const int bcol = (lane >> 4) * 8;

    #pragma unroll
    for (int ks = 0; ks < 8; ks++) {
        uint32_t a[2][4];
        #pragma unroll
        for (int mt = 0; mt < 2; mt++) {
            uint32_t addr = Ab + (uint32_t)((mt * 16 + arow) * K1_SA + ks * 16 + acol) * 2;
            LDSM4(a[mt][0], a[mt][1], a[mt][2], a[mt][3], addr);
        }
        #pragma unroll
        for (int np = 0; np < 2; np++) {
            uint32_t b0, b1, b2, b3;
            uint32_t addr = Xb + (uint32_t)((ks * 16 + brow) * K1_SX + nh * 32 + np * 16 + bcol) * 2;
            LDSM4T(b0, b1, b2, b3, addr);
            #pragma unroll
            for (int mt = 0; mt < 2; mt++) {
                MMA16816(acc[mt][np * 2],     a[mt][0], a[mt][1], a[mt][2], a[mt][3], b0, b1);
                MMA16816(acc[mt][np * 2 + 1], a[mt][0], a[mt][1], a[mt][2], a[mt][3], b2, b3);
            }
        }
    }

    // epilogue: write bf16 P1b[b][ky][h*2+p][c]
    const int h = hg * 4 + hl;
    #pragma unroll
    for (int mt = 0; mt < 2; mt++)
        #pragma unroll
        for (int nt = 0; nt < 4; nt++)
            #pragma unroll
            for (int half = 0; half < 2; half++) {
                int m = mt * 16 + (lane >> 2) + half * 8;
                int ky = m >> 1, p = m & 1;
                int c = nh * 32 + nt * 8 + 2 * (lane & 3);
                uint32_t v = pack2(__float2bfloat16_rn(acc[mt][nt][half * 2]),
                                   __float2bfloat16_rn(acc[mt][nt][half * 2 + 1]));
                *(uint32_t*)&g_P1b[(((size_t)b * 16 + ky) * 256 + h * 2 + p) * 64 + c] = v;
            }
}

// ---------------------------------------------------------------------------
// K2 (mma): per (b,ky): X[64 m=(kxi,p), 64 c] = G2[64x256] @ P1b[256,64]
// ---------------------------------------------------------------------------
#define K2_SA 264
#define K2_SMEM_A 0
#define K2_SMEM_B (64 * K2_SA * 2)                       // 33792
#define K2_SMEM_TOTAL (K2_SMEM_B + 256 * K1_SX * 2)      // 70656

__global__ __launch_bounds__(256) void k2_mma()
{
    extern __shared__ char sm[];
    const uint32_t sbase = smem_u32(sm);
    const int b    = blockIdx.x >> 4;
    const int ky   = blockIdx.x & 15;
    const int t    = threadIdx.x;
    const int warp = t >> 5;
    const int lane = t & 31;

    {
        const uint32_t* ga = (const uint32_t*)g_G2;
        for (int i = t; i < 64 * 128; i += 256) {
            int m = i >> 7, kp = i & 127;
            *(uint32_t*)(sm + K2_SMEM_A + (m * K2_SA + kp * 2) * 2) = ga[i];
        }
        const uint32_t* gb = (const uint32_t*)(g_P1b + ((size_t)(b * 16 + ky)) * 256 * 64);
        for (int i = t; i < 256 * 32; i += 256) {
            int r = i >> 5, cp = i & 31;
            *(uint32_t*)(sm + K2_SMEM_B + (r * K1_SX + cp * 2) * 2) = gb[i];
        }
    }
    __syncthreads();

    const int mi = warp >> 1, nh = warp & 1;
    float acc[4][4];
    #pragma unroll
    for (int nt = 0; nt < 4; nt++)
        #pragma unroll
        for (int q = 0; q < 4; q++) acc[nt][q] = 0.f;

    const int arow = lane & 15;
    const int acol = (lane >> 4) * 8;
    const int brow = (lane & 7) + ((lane >> 3) & 1) * 8;
    const int bcol = (lane >> 4) * 8;

    #pragma unroll
    for (int ks = 0; ks < 16; ks++) {
        uint32_t a0, a1, a2, a3;
        uint32_t aaddr = sbase + K2_SMEM_A + (uint32_t)((mi * 16 + arow) * K2_SA + ks * 16 + acol) * 2;
        LDSM4(a0, a1, a2, a3, aaddr);
        #pragma unroll
        for (int np = 0; np < 2; np++) {
            uint32_t b0, b1, b2, b3;
            uint32_t baddr = sbase + K2_SMEM_B
                + (uint32_t)((ks * 16 + brow) * K1_SX + nh * 32 + np * 16 + bcol) * 2;
            LDSM4T(b0, b1, b2, b3, baddr);
            MMA16816(acc[np * 2],     a0, a1, a2, a3, b0, b1);
            MMA16816(acc[np * 2 + 1], a0, a1, a2, a3, b2, b3);
        }
    }

    #pragma unroll
    for (int nt = 0; nt < 4; nt++)
        #pragma unroll
        for (int half = 0; half < 2; half++) {
            int m = mi * 16 + (lane >> 2) + half * 8;
            int kxi = m >> 1, p = m & 1;
            int c = nh * 32 + nt * 8 + 2 * (lane & 3);
            float* dst = (p == 0 ? g_Xr : g_Xi) + (((size_t)b * NKX + kxi) * MY + ky) * CC + c;
            *(float2*)dst = make_float2(acc[nt][half * 2], acc[nt][half * 2 + 1]);
        }
}

// ---------------------------------------------------------------------------
// K3: complex mode mixing (fp32, unchanged)
// ---------------------------------------------------------------------------
__global__ __launch_bounds__(256) void k3_mix(const float* __restrict__ w1r,
                                              const float* __restrict__ w1i,
                                              const float* __restrict__ w2r,
                                              const float* __restrict__ w2i)
{
    __shared__ float Xsr[BB * CC], Xsi[BB * CC];
    __shared__ float Wsr[CC * CC], Wsi[CC * CC];
    const int kxi = blockIdx.x >> 4;
    const int ky  = blockIdx.x & 15;
    const int t   = threadIdx.x;

    const float* wr;
    const float* wi;
    if (kxi < 16) {
        size_t off = (size_t)(kxi * 16 + ky) * CC * CC;
        wr = w1r + off; wi = w1i + off;
    } else {
        size_t off = (size_t)((kxi - 16) * 16 + ky) * CC * CC;
        wr = w2r + off; wi = w2i + off;
    }
    for (int i = t; i < CC * CC / 4; i += 256) {
        ((float4*)Wsr)[i] = ((const float4*)wr)[i];
        ((float4*)Wsi)[i] = ((const float4*)wi)[i];
    }
    for (int i = t; i < BB * CC; i += 256) {
        int b = i >> 6, c = i & 63;
        size_t src = (((size_t)b * NKX + kxi) * MY + ky) * CC + c;
        Xsr[i] = g_Xr[src];
        Xsi[i] = g_Xi[src];
    }
    __syncthreads();

    const int o  = t & 63;
    const int bg = t >> 6;
    float yr[8], yi[8];
    #pragma unroll
    for (int j = 0; j < 8; j++) { yr[j] = 0.f; yi[j] = 0.f; }

    for (int i = 0; i < CC; i++) {
        float wrv = Wsr[i * 64 + o];
        float wiv = Wsi[i * 64 + o];
        #pragma unroll
        for (int j = 0; j < 8; j++) {
            int b = bg * 8 + j;
            float xr = Xsr[b * 64 + i];
            float xi = Xsi[b * 64 + i];
            yr[j] += xr * wrv - xi * wiv;
            yi[j] += xr * wiv + xi * wrv;
        }
    }
    #pragma unroll
    for (int j = 0; j < 8; j++) {
        size_t dst = (((size_t)(bg * 8 + j) * NKX + kxi) * MY + ky) * CC + o;
        g_Yr[dst] = yr[j];
        g_Yi[dst] = yi[j];
    }
}

// ---------------------------------------------------------------------------
// K4: inverse DFT along H (fp32, unchanged)
// ---------------------------------------------------------------------------
__global__ __launch_bounds__(256) void k4_invH()
{
    __shared__ float  Ysr[NKX * CC], Ysi[NKX * CC];
    __shared__ float2 tw[HH * NKX];
    const int b  = blockIdx.x >> 4;
    const int ky = blockIdx.x & 15;
    const int t  = threadIdx.x;

    for (int i = t; i < HH * NKX; i += 256) {
        int h = i >> 5, kxi = i & 31;
        int kx = (kxi < 16) ? kxi : (96 + kxi);
        float s, c;
        sincospif((float)(kx * h) * (1.0f / 64.0f), &s, &c);
        tw[i] = make_float2(c * (1.0f / 128.0f), s * (1.0f / 128.0f));
    }
    for (int i = t; i < NKX * CC; i += 256) {
        int kxi = i >> 6, c = i & 63;
        size_t src = (((size_t)b * NKX + kxi) * MY + ky) * CC + c;
        Ysr[i] = g_Yr[src];
        Ysi[i] = g_Yi[src];
    }
    __syncthreads();

    const int c  = t & 63;
    const int hg = t >> 6;
    float yrr[NKX], yii[NKX];
    #pragma unroll
    for (int k = 0; k < NKX; k++) {
        yrr[k] = Ysr[k * 64 + c];
        yii[k] = Ysi[k * 64 + c];
    }
    for (int j = 0; j < 32; j++) {
        int h = hg * 32 + j;
        float zr = 0.f, zi = 0.f;
        const float4* twr = (const float4*)(tw + h * NKX);
        #pragma unroll
        for (int q = 0; q < 16; q++) {
            float4 tq = twr[q];
            zr += yrr[2 * q] * tq.x - yii[2 * q] * tq.y;
            zi += yrr[2 * q] * tq.y + yii[2 * q] * tq.x;
            zr += yrr[2 * q + 1] * tq.z - yii[2 * q + 1] * tq.w;
            zi += yrr[2 * q + 1] * tq.w + yii[2 * q + 1] * tq.z;
        }
        size_t o = (((size_t)b * HH + h) * MY + ky) * CC + c;
        g_Zr[o] = zr;
        g_Zi[o] = zi;
    }
}

// ---------------------------------------------------------------------------
// K5: mma.sync bf16 GEMM per (b,h) (unchanged from R3)
// ---------------------------------------------------------------------------
#define SA 168
#define K5_BIAS 0
#define K5_A    256
#define K5_B    (256 + 128 * SA * 2)
#define K5_SMEM (K5_B + 64 * SA * 2)

__global__ __launch_bounds__(256) void k5_mma(const float* __restrict__ x,
                                              const float* __restrict__ bias,
                                              float* __restrict__ out)
{
    extern __shared__ char smem[];
    const uint32_t sbase = smem_u32(smem);
    const int bh   = blockIdx.x;
    const int t    = threadIdx.x;
    const int warp = t >> 5;
    const int lane = t & 31;

    {
        const int w  = t >> 1;
        const int c0 = (t & 1) * 32;
        const float4* xr4 = (const float4*)(x + (size_t)bh * 8192 + (size_t)w * 64 + c0);
        #pragma unroll
        for (int ch = 0; ch < 4; ch++) {
            uint32_t uh[2], ul[2];
            #pragma unroll
            for (int q = 0; q < 2; q++) {
                float4 v = xr4[ch * 2 + q];
                __nv_bfloat16 h0 = __float2bfloat16_rn(v.x), h1 = __float2bfloat16_rn(v.y);
                __nv_bfloat16 h2 = __float2bfloat16_rn(v.z), h3 = __float2bfloat16_rn(v.w);
                uh[q] = pack2(h0, h1);
                ul[q] = pack2(__float2bfloat16_rn(v.x - __bfloat162float(h0)),
                              __float2bfloat16_rn(v.y - __bfloat162float(h1)));
                uint32_t uh2 = pack2(h2, h3);
                uint32_t ul2 = pack2(__float2bfloat16_rn(v.z - __bfloat162float(h2)),
                                     __float2bfloat16_rn(v.w - __bfloat162float(h3)));
                if (q == 0) { *(uint2*)(smem + K5_A + (w * SA + c0 + ch * 8) * 2)      = make_uint2(uh[0], uh2);
                              *(uint2*)(smem + K5_A + (w * SA + 64 + c0 + ch * 8) * 2) = make_uint2(ul[0], ul2); }
                else        { *(uint2*)(smem + K5_A + (w * SA + c0 + ch * 8 + 4) * 2)      = make_uint2(uh[1], uh2);
                              *(uint2*)(smem + K5_A + (w * SA + 64 + c0 + ch * 8 + 4) * 2) = make_uint2(ul[1], ul2); }
            }
        }
    }
    if (t < 128) {
        const int w = t;
        const uint4* ts = (const uint4*)(g_T + w * 32);
        #pragma unroll
        for (int ch = 0; ch < 4; ch++)
            *(uint4*)(smem + K5_A + (w * SA + 128 + ch * 8) * 2) = ts[ch];
    }
    {
        const int c = t >> 2;
        const int q = t & 3;
        if (q < 2) {
            const uint4* src = (const uint4*)(g_Bk + c * 128 + q * 64);
            #pragma unroll
            for (int ch = 0; ch < 8; ch++)
                *(uint4*)(smem + K5_B + (c * SA + q * 64 + ch * 8) * 2) = src[ch];
        } else {
            const float* zsrc = (q == 2) ? g_Zr : g_Zi;
            const size_t zb = (size_t)bh * MY * CC + c;
            uint32_t u[8];
            #pragma unroll
            for (int k = 0; k < 8; k++)
                u[k] = pack2(__float2bfloat16_rn(zsrc[zb + (size_t)(2 * k) * CC]),
                             __float2bfloat16_rn(zsrc[zb + (size_t)(2 * k + 1) * CC]));
            int col = 128 + (q - 2) * 16;
            *(uint4*)(smem + K5_B + (c * SA + col) * 2)     = make_uint4(u[0], u[1], u[2], u[3]);
            *(uint4*)(smem + K5_B + (c * SA + col + 8) * 2) = make_uint4(u[4], u[5], u[6], u[7]);
        }
    }
    if (t < 64) ((float*)(smem + K5_BIAS))[t] = bias[t];

    __syncthreads();

    float acc[8][4];
    #pragma unroll
    for (int nt = 0; nt < 8; nt++) {
        acc[nt][0] = 0.f; acc[nt][1] = 0.f; acc[nt][2] = 0.f; acc[nt][3] = 0.f;
    }

    const int arow  = warp * 16 + (lane & 7) + ((lane >> 3) & 1) * 8;
    const int akoff = (lane >> 4) * 8;
    const int brow  = (lane & 7) + (lane >> 4) * 8;
    const int bkoff = ((lane >> 3) & 1) * 8;

    const int passes[4][3] = { {0, 0, 4}, {0, 64, 4}, {64, 0, 4}, {128, 128, 2} };
    #pragma unroll
    for (int p = 0; p < 4; p++) {
        const int kA = passes[p][0], kB = passes[p][1], nks = passes[p][2];
        #pragma unroll
        for (int ks = 0; ks < 4; ks++) {
            if (ks >= nks) break;
            uint32_t a0, a1, a2, a3;
            uint32_t aaddr = sbase + K5_A + (uint32_t)(arow * SA + kA + ks * 16 + akoff) * 2;
            LDSM4(a0, a1, a2, a3, aaddr);
            #pragma unroll
            for (int nt2 = 0; nt2 < 4; nt2++) {
                uint32_t b0, b1, b2, b3;
                uint32_t baddr = sbase + K5_B
                    + (uint32_t)((nt2 * 16 + brow) * SA + kB + ks * 16 + bkoff) * 2;
                LDSM4(b0, b1, b2, b3, baddr);
                MMA16816(acc[2 * nt2],     a0, a1, a2, a3, b0, b1);
                MMA16816(acc[2 * nt2 + 1], a0, a1, a2, a3, b2, b3);
            }
        }
    }

    const int r0 = warp * 16 + (lane >> 2);
    const float* bs = (const float*)(smem + K5_BIAS);
    #pragma unroll
    for (int half = 0; half < 2; half++) {
        const int r = r0 + half * 8;
        float* orow = out + (size_t)bh * 8192 + (size_t)r * 64;
        #pragma unroll
        for (int nt = 0; nt < 8; nt++) {
            const int c = nt * 8 + 2 * (lane & 3);
            uint32_t hp = *(const uint32_t*)(smem + K5_A + (r * SA + c) * 2);
            uint32_t lp = *(const uint32_t*)(smem + K5_A + (r * SA + 64 + c) * 2);
            float res0 = bflo(hp) + bflo(lp);
            float res1 = bfhi(hp) + bfhi(lp);
            float s0 = acc[nt][half * 2 + 0] + res0 + bs[c];
            float s1 = acc[nt][half * 2 + 1] + res1 + bs[c + 1];
            float u0 = 0.7978845608028654f * (s0 + 0.044715f * s0 * s0 * s0);
            float u1 = 0.7978845608028654f * (s1 + 0.044715f * s1 * s1 * s1);
            float g0 = s0 * __frcp_rn(1.0f + __expf(-2.0f * u0));
            float g1 = s1 * __frcp_rn(1.0f + __expf(-2.0f * u1));
            *(float2*)(orow + c) = make_float2(g0, g1);
        }
    }
}

// ---------------------------------------------------------------------------
// Launch
// ---------------------------------------------------------------------------
extern "C" void kernel_launch(void* const* d_in, const int* in_sizes, int n_in,
                              void* d_out, int out_size)
{
    const float* x   = (const float*)d_in[0];
    const float* w1r = (const float*)d_in[1];
    const float* w1i = (const float*)d_in[2];
    const float* w2r = (const float*)d_in[3];
    const float* w2i = (const float*)d_in[4];
    const float* dk  = (const float*)d_in[5];
    const float* db  = (const float*)d_in[6];
    float* out = (float*)d_out;

    static int configured = 0;
    if (!configured) {
        cudaFuncSetAttribute(k1_mma, cudaFuncAttributeMaxDynamicSharedMemorySize, K1_SMEM_TOTAL);
        cudaFuncSetAttribute(k2_mma, cudaFuncAttributeMaxDynamicSharedMemorySize, K2_SMEM_TOTAL);
        cudaFuncSetAttribute(k5_mma, cudaFuncAttributeMaxDynamicSharedMemorySize, K5_SMEM);
        configured = 1;
    }

    k0_init <<<48, 256>>>(dk);
    k1_mma  <<<BB * 32, 256, K1_SMEM_TOTAL>>>(x);
    k2_mma  <<<BB * MY, 256, K2_SMEM_TOTAL>>>();
    k3_mix  <<<NKX * MY, 256>>>(w1r, w1i, w2r, w2i);
    k4_invH <<<BB * MY, 256>>>();
    k5_mma  <<<BB * HH, 256, K5_SMEM>>>(x, db, out);
}